// round 5
// baseline (speedup 1.0000x reference)
#include <cuda_runtime.h>
#include <cstdint>

#define S_TOK 8192
#define D_DIM 2048
#define E_EXP 64
#define CAP   128

// ---------------- scratch ----------------
__device__ int   g_idx[S_TOK];
__device__ float g_gate1[S_TOK];
__device__ float g_partialGateSum[128 * E_EXP];   // per-gemm-block softmax sums

// ---------------- packed fp32x2 helpers (Blackwell FFMA2) ----------------
__device__ __forceinline__ uint64_t pack2(float lo, float hi) {
    uint64_t p;
    asm("mov.b64 %0, {%1, %2};" : "=l"(p) : "f"(lo), "f"(hi));
    return p;
}
__device__ __forceinline__ void unpack2(uint64_t p, float& lo, float& hi) {
    asm("mov.b64 {%0, %1}, %2;" : "=f"(lo), "=f"(hi) : "l"(p));
}
#define FMA2(d, a, b) asm("fma.rn.f32x2 %0, %1, %2, %0;" : "+l"(d) : "l"(a), "l"(b))

// ---------------- fused GEMM+softmax + output zeroing ----------------
// Blocks 0..127   : 64-token x 64-expert GEMM tile (256 thr, 4x4 thread tile, FFMA2)
// Blocks 128..1919: zero-fill d_out (concurrent, soaks idle DRAM + issue slots)
#define GEMM_BLOCKS 128
#define ZERO_BLOCKS 1792
#define BM 64
#define BN 64
#define BK 32
#define SROW 68   // padded row stride

__global__ void __launch_bounds__(256) fused_kernel(const float* __restrict__ x,
                                                    const float* __restrict__ wg,
                                                    float* __restrict__ out,
                                                    long long out_elems) {
    // ---------- zero role ----------
    if (blockIdx.x >= GEMM_BLOCKS) {
        const long long zb = blockIdx.x - GEMM_BLOCKS;
        const long long total4 = out_elems >> 2;
        float4* o4 = (float4*)out;
        const float4 z = make_float4(0.f, 0.f, 0.f, 0.f);
        const long long stride = (long long)ZERO_BLOCKS * 256;
        for (long long i = zb * 256 + threadIdx.x; i < total4; i += stride) o4[i] = z;
        if (zb == 0 && threadIdx.x == 0)
            for (long long i = total4 * 4; i < out_elems; i++) out[i] = 0.f;
        return;
    }

    // ---------- GEMM role ----------
    __shared__ float sm[2 * BK * SROW];       // Xs[32][68] | Ws[32][68]; reused as Ls[64][68]
    __shared__ float pg[8 * E_EXP];
    float (*Xs)[SROW] = (float(*)[SROW])sm;
    float (*Ws)[SROW] = (float(*)[SROW])(sm + BK * SROW);
    float (*Ls)[SROW] = (float(*)[SROW])sm;

    const int tid = threadIdx.x;
    const int m0  = blockIdx.x * BM;
    const int tx  = tid & 15;    // expert group: tx*4..tx*4+3
    const int ty  = tid >> 4;    // token  group: ty*4..ty*4+3

    int rowi[2], c4i[2];
#pragma unroll
    for (int i = 0; i < 2; i++) {
        int f = tid + i * 256;   // 512 float4 per 64x32 tile
        rowi[i] = f >> 3;
        c4i[i]  = f & 7;
    }

    float4 xr[2], wr[2];
#pragma unroll
    for (int i = 0; i < 2; i++) {
        xr[i] = *(const float4*)(x  + (size_t)(m0 + rowi[i]) * D_DIM + c4i[i] * 4);
        wr[i] = *(const float4*)(wg + (size_t)rowi[i] * D_DIM + c4i[i] * 4);
    }

    uint64_t acc2[4][2];   // 4 tokens x (2 expert-pairs), packed f32x2
#pragma unroll
    for (int i = 0; i < 4; i++) { acc2[i][0] = 0ull; acc2[i][1] = 0ull; }

    const int NT = D_DIM / BK;
    for (int kt = 0; kt < NT; kt++) {
#pragma unroll
        for (int i = 0; i < 2; i++) {
            int c = c4i[i] * 4, r = rowi[i];
            Xs[c + 0][r] = xr[i].x; Xs[c + 1][r] = xr[i].y;
            Xs[c + 2][r] = xr[i].z; Xs[c + 3][r] = xr[i].w;
            Ws[c + 0][r] = wr[i].x; Ws[c + 1][r] = wr[i].y;
            Ws[c + 2][r] = wr[i].z; Ws[c + 3][r] = wr[i].w;
        }
        __syncthreads();

        if (kt + 1 < NT) {
            int k0 = (kt + 1) * BK;
#pragma unroll
            for (int i = 0; i < 2; i++) {
                xr[i] = *(const float4*)(x  + (size_t)(m0 + rowi[i]) * D_DIM + k0 + c4i[i] * 4);
                wr[i] = *(const float4*)(wg + (size_t)rowi[i] * D_DIM + k0 + c4i[i] * 4);
            }
        }

#pragma unroll
        for (int k = 0; k < BK; k++) {
            float4 a4 = *(const float4*)&Xs[k][ty * 4];
            float4 b4 = *(const float4*)&Ws[k][tx * 4];
            uint64_t bp0 = pack2(b4.x, b4.y);
            uint64_t bp1 = pack2(b4.z, b4.w);
            uint64_t a0  = pack2(a4.x, a4.x);
            uint64_t a1  = pack2(a4.y, a4.y);
            uint64_t a2  = pack2(a4.z, a4.z);
            uint64_t a3  = pack2(a4.w, a4.w);
            FMA2(acc2[0][0], a0, bp0); FMA2(acc2[0][1], a0, bp1);
            FMA2(acc2[1][0], a1, bp0); FMA2(acc2[1][1], a1, bp1);
            FMA2(acc2[2][0], a2, bp0); FMA2(acc2[2][1], a2, bp1);
            FMA2(acc2[3][0], a3, bp0); FMA2(acc2[3][1], a3, bp1);
        }
        __syncthreads();
    }

    // ---------- softmax epilogue ----------
#pragma unroll
    for (int i = 0; i < 4; i++) {
        float4 v;
        unpack2(acc2[i][0], v.x, v.y);
        unpack2(acc2[i][1], v.z, v.w);
        *(float4*)&Ls[ty * 4 + i][tx * 4] = v;
    }
    __syncthreads();

    const int wpid = tid >> 5, lane = tid & 31;
    float pa0 = 0.0f, pa1 = 0.0f;
#pragma unroll
    for (int t = 0; t < 8; t++) {
        const int row = wpid * 8 + t;
        float l0 = Ls[row][lane];
        float l1 = Ls[row][lane + 32];
        float mv; int mi;                     // argmax, first-occurrence tie-break
        if (l0 >= l1) { mv = l0; mi = lane; } else { mv = l1; mi = lane + 32; }
#pragma unroll
        for (int off = 16; off; off >>= 1) {
            float ov = __shfl_down_sync(0xffffffffu, mv, off);
            int   oi = __shfl_down_sync(0xffffffffu, mi, off);
            if (ov > mv || (ov == mv && oi < mi)) { mv = ov; mi = oi; }
        }
        mv = __shfl_sync(0xffffffffu, mv, 0);
        mi = __shfl_sync(0xffffffffu, mi, 0);

        float e0 = expf(l0 - mv), e1 = expf(l1 - mv);
        float sum = e0 + e1;
#pragma unroll
        for (int off = 16; off; off >>= 1) sum += __shfl_down_sync(0xffffffffu, sum, off);
        sum = __shfl_sync(0xffffffffu, sum, 0);
        float inv = 1.0f / sum;

        pa0 += e0 * inv;
        pa1 += e1 * inv;
        if (lane == 0) { g_idx[m0 + row] = mi; g_gate1[m0 + row] = inv; }
    }
    pg[wpid * E_EXP + lane]      = pa0;
    pg[wpid * E_EXP + lane + 32] = pa1;
    __syncthreads();
    if (tid < E_EXP) {
        float s = 0.0f;
#pragma unroll
        for (int w8 = 0; w8 < 8; w8++) s += pg[w8 * E_EXP + tid];
        g_partialGateSum[(size_t)blockIdx.x * E_EXP + tid] = s;
    }
}

// ---------------- scan + aux + scatter (single block; zeros already done) ----------------
__global__ void __launch_bounds__(1024) scan_scatter_kernel(float* __restrict__ combine,
                                                            float* __restrict__ maskp,
                                                            float* __restrict__ lauxp) {
    __shared__ int   hist[32 * E_EXP];
    __shared__ float red[16 * E_EXP];
    __shared__ int   cntS[E_EXP];
    __shared__ float vals[E_EXP];

    const int tid = threadIdx.x, lane = tid & 31, w = tid >> 5;
    hist[tid] = 0; hist[tid + 1024] = 0;
    __syncthreads();

    // phase 1: warp-local ordered ranks over 256 contiguous tokens
    int eArr[8], locArr[8];
    const int base = w * 256;
#pragma unroll
    for (int g = 0; g < 8; g++) {
        const int s = base + g * 32 + lane;
        const int e = g_idx[s];
        unsigned mask = __match_any_sync(0xffffffffu, e);
        int rank = __popc(mask & ((1u << lane) - 1u));
        int bcnt = hist[w * E_EXP + e];
        eArr[g] = e; locArr[g] = bcnt + rank;
        __syncwarp();
        if (lane == __ffs(mask) - 1) hist[w * E_EXP + e] = bcnt + __popc(mask);
        __syncwarp();
    }
    __syncthreads();

    // phase 2: exclusive prefix across warps, per expert
    if (tid < E_EXP) {
        int running = 0;
        for (int ww = 0; ww < 32; ww++) {
            int c = hist[ww * E_EXP + tid];
            hist[ww * E_EXP + tid] = running;
            running += c;
        }
        cntS[tid] = running;
    }
    __syncthreads();

    // phase 3: scatter combine + mask directly (capacity drop)
#pragma unroll
    for (int g = 0; g < 8; g++) {
        const int s   = base + g * 32 + lane;
        const int e   = eArr[g];
        const int loc = hist[w * E_EXP + e] + locArr[g];
        if (loc < CAP) {
            const size_t off = (size_t)s * (E_EXP * CAP) + (size_t)e * CAP + loc;
            const float gv = g_gate1[s];
            combine[off] = gv;
            if (maskp) maskp[off] = 1.0f;
        }
    }

    // phase 4: aux loss (deterministic fixed-order)
    {
        const int e = tid & 63, r = tid >> 6;  // 16 slices x 64 experts
        float sum = 0.0f;
        for (int p = r * 8; p < r * 8 + 8; p++) sum += g_partialGateSum[(size_t)p * E_EXP + e];
        red[(size_t)r * E_EXP + e] = sum;
    }
    __syncthreads();
    if (tid < E_EXP) {
        float me = 0.0f;
#pragma unroll
        for (int r = 0; r < 16; r++) me += red[r * E_EXP + tid];
        me /= (float)S_TOK;
        float ce = (float)cntS[tid] / (float)S_TOK;
        vals[tid] = me * ce;
    }
    __syncthreads();
    if (tid == 0 && lauxp) {
        float a = 0.0f;
        for (int e = 0; e < E_EXP; e++) a += vals[e];
        lauxp[0] = a * (float)E_EXP;   // mean * E*E == sum * E
    }
}

// ---------------- launch ----------------
extern "C" void kernel_launch(void* const* d_in, const int* in_sizes, int n_in,
                              void* d_out, int out_size) {
    const float* x  = (const float*)d_in[0];   // [S, D]
    const float* wg = (const float*)d_in[1];   // [E, D]
    float* out = (float*)d_out;

    const long long SEC = (long long)S_TOK * E_EXP * CAP;  // 67,108,864
    float* lauxp   = nullptr;
    float* combine = out;
    float* maskp   = nullptr;
    if ((long long)out_size >= 1 + 2 * SEC) {          // [l_aux, combine, mask]
        lauxp = out; combine = out + 1; maskp = out + 1 + SEC;
    } else if ((long long)out_size == 1 + SEC) {       // [l_aux, combine]
        lauxp = out; combine = out + 1;
    }

    fused_kernel<<<GEMM_BLOCKS + ZERO_BLOCKS, 256>>>(x, wg, out, (long long)out_size);
    scan_scatter_kernel<<<1, 1024>>>(combine, maskp, lauxp);
}

// round 11
// speedup vs baseline: 1.4746x; 1.4746x over previous
#include <cuda_runtime.h>
#include <cuda_bf16.h>
#include <cstdint>

#define S_TOK 8192
#define D_DIM 2048
#define E_EXP 64
#define CAP   128

// ---------------- scratch ----------------
__device__ int   g_idx[S_TOK];
__device__ float g_gate1[S_TOK];
__device__ float g_partialGateSum[128 * E_EXP];   // per-CTA softmax expert sums

// ---------------- helpers ----------------
__device__ __forceinline__ void mma_bf16(float c[4], uint32_t a0, uint32_t a1, uint32_t a2, uint32_t a3,
                                         uint32_t b0, uint32_t b1) {
    asm volatile(
        "mma.sync.aligned.m16n8k16.row.col.f32.bf16.bf16.f32 "
        "{%0,%1,%2,%3}, {%4,%5,%6,%7}, {%8,%9}, {%0,%1,%2,%3};"
        : "+f"(c[0]), "+f"(c[1]), "+f"(c[2]), "+f"(c[3])
        : "r"(a0), "r"(a1), "r"(a2), "r"(a3), "r"(b0), "r"(b1));
}
// bf16 two-term split: f = hi + lo + O(2^-18 f)
__device__ __forceinline__ void split_bf16(float f, uint16_t& h, uint16_t& l) {
    __nv_bfloat16 bh = __float2bfloat16(f);
    float rem = f - __bfloat162float(bh);
    __nv_bfloat16 bl = __float2bfloat16(rem);
    h = __bfloat16_as_ushort(bh);
    l = __bfloat16_as_ushort(bl);
}
__device__ __forceinline__ uint64_t pack4(uint16_t a, uint16_t b, uint16_t c, uint16_t d) {
    return (uint64_t)a | ((uint64_t)b << 16) | ((uint64_t)c << 32) | ((uint64_t)d << 48);
}

// ================= HMMA GEMM + softmax =================
// 128 CTAs x 256 threads. CTA tile: 64 tokens x 64 experts, K in 32 chunks of 64.
// 4-term bf16-split mma.sync (hh+hl+lh+ll) into fp32 accumulators.
// smem rows padded to 72 bf16 (144B) -> conflict-free staging + fragment loads.
#define KC     64
#define NCHUNK (D_DIM / KC)          // 32
#define SROWH  72                    // bf16 elements per padded row
#define TILE_B (64 * SROWH * 2)      // 9216 bytes per h/l tile
#define OFF_AH 0
#define OFF_AL (TILE_B)
#define OFF_BH (2 * TILE_B)
#define OFF_BL (3 * TILE_B)

__global__ void __launch_bounds__(256) gemm_mma_kernel(const float* __restrict__ x,
                                                       const float* __restrict__ wg) {
    __shared__ __align__(16) char smbuf[4 * TILE_B];   // 36864 B; reused by epilogue

    const int tid  = threadIdx.x;
    const int lane = tid & 31;
    const int w    = tid >> 5;
    const int m0   = blockIdx.x * 64;
    const int M0   = (w & 3) * 16;        // warp token sub-tile
    const int N0   = (w >> 2) * 32;       // warp expert half

    // staging coordinates: 64 rows x 16 float4, 4 per thread
    int rr[4], cc[4];
#pragma unroll
    for (int t = 0; t < 4; t++) { int f = tid + t * 256; rr[t] = f >> 4; cc[t] = (f & 15) * 4; }

    float acc[4][4];
#pragma unroll
    for (int nt = 0; nt < 4; nt++)
#pragma unroll
        for (int j = 0; j < 4; j++) acc[nt][j] = 0.0f;

    // prefetch chunk 0
    float4 av[4], bv[4];
#pragma unroll
    for (int t = 0; t < 4; t++) {
        av[t] = *(const float4*)(x  + (size_t)(m0 + rr[t]) * D_DIM + cc[t]);
        bv[t] = *(const float4*)(wg + (size_t)rr[t] * D_DIM + cc[t]);
    }

    const uint32_t* AH32 = (const uint32_t*)(smbuf + OFF_AH);
    const uint32_t* AL32 = (const uint32_t*)(smbuf + OFF_AL);
    const uint32_t* BH32 = (const uint32_t*)(smbuf + OFF_BH);
    const uint32_t* BL32 = (const uint32_t*)(smbuf + OFF_BL);

    for (int i = 0; i < NCHUNK; i++) {
        // ---- stage current chunk (split fp32 -> bf16 h/l) ----
#pragma unroll
        for (int t = 0; t < 4; t++) {
            uint16_t h0, l0, h1, l1, h2, l2, h3, l3;
            const uint32_t off = (uint32_t)(rr[t] * SROWH + cc[t]) * 2;
            split_bf16(av[t].x, h0, l0); split_bf16(av[t].y, h1, l1);
            split_bf16(av[t].z, h2, l2); split_bf16(av[t].w, h3, l3);
            *(uint64_t*)(smbuf + OFF_AH + off) = pack4(h0, h1, h2, h3);
            *(uint64_t*)(smbuf + OFF_AL + off) = pack4(l0, l1, l2, l3);
            split_bf16(bv[t].x, h0, l0); split_bf16(bv[t].y, h1, l1);
            split_bf16(bv[t].z, h2, l2); split_bf16(bv[t].w, h3, l3);
            *(uint64_t*)(smbuf + OFF_BH + off) = pack4(h0, h1, h2, h3);
            *(uint64_t*)(smbuf + OFF_BL + off) = pack4(l0, l1, l2, l3);
        }
        __syncthreads();

        // ---- prefetch next chunk (overlaps MMA phase) ----
        if (i + 1 < NCHUNK) {
            const int kc = (i + 1) * KC;
#pragma unroll
            for (int t = 0; t < 4; t++) {
                av[t] = *(const float4*)(x  + (size_t)(m0 + rr[t]) * D_DIM + kc + cc[t]);
                bv[t] = *(const float4*)(wg + (size_t)rr[t] * D_DIM + kc + cc[t]);
            }
        }

        // ---- MMA phase: 4 k16-steps, 4 n8-tiles, 4 split terms ----
#pragma unroll
        for (int ks = 0; ks < 4; ks++) {
            const int kq = ks * 16 + (lane & 3) * 2;
            const int mA = M0 + (lane >> 2);
            const uint32_t ah0 = AH32[(mA * SROWH + kq) >> 1];
            const uint32_t ah1 = AH32[((mA + 8) * SROWH + kq) >> 1];
            const uint32_t ah2 = AH32[(mA * SROWH + kq + 8) >> 1];
            const uint32_t ah3 = AH32[((mA + 8) * SROWH + kq + 8) >> 1];
            const uint32_t al0 = AL32[(mA * SROWH + kq) >> 1];
            const uint32_t al1 = AL32[((mA + 8) * SROWH + kq) >> 1];
            const uint32_t al2 = AL32[(mA * SROWH + kq + 8) >> 1];
            const uint32_t al3 = AL32[((mA + 8) * SROWH + kq + 8) >> 1];
#pragma unroll
            for (int nt = 0; nt < 4; nt++) {
                const int nB = N0 + nt * 8 + (lane >> 2);
                const uint32_t bh0 = BH32[(nB * SROWH + kq) >> 1];
                const uint32_t bh1 = BH32[(nB * SROWH + kq + 8) >> 1];
                const uint32_t bl0 = BL32[(nB * SROWH + kq) >> 1];
                const uint32_t bl1 = BL32[(nB * SROWH + kq + 8) >> 1];
                mma_bf16(acc[nt], ah0, ah1, ah2, ah3, bh0, bh1);
                mma_bf16(acc[nt], ah0, ah1, ah2, ah3, bl0, bl1);
                mma_bf16(acc[nt], al0, al1, al2, al3, bh0, bh1);
                mma_bf16(acc[nt], al0, al1, al2, al3, bl0, bl1);
            }
        }
        __syncthreads();
    }

    // ---------- epilogue: logits -> smem, per-token softmax ----------
    float* Ls  = (float*)smbuf;            // [64][65] padded (stride 65 -> conflict-free columns)
    float* pg  = Ls + 64 * 65;             // [64][65]
    float* red = pg + 64 * 65;             // [4][64]
    {
        const int r0 = M0 + (lane >> 2);
        const int cb = (lane & 3) * 2;
#pragma unroll
        for (int nt = 0; nt < 4; nt++) {
            const int c0 = N0 + nt * 8 + cb;
            Ls[r0 * 65 + c0]           = acc[nt][0];
            Ls[r0 * 65 + c0 + 1]       = acc[nt][1];
            Ls[(r0 + 8) * 65 + c0]     = acc[nt][2];
            Ls[(r0 + 8) * 65 + c0 + 1] = acc[nt][3];
        }
    }
    __syncthreads();

    if (tid < 64) {
        float mv = -3.4e38f; int mi = 0;
#pragma unroll
        for (int e = 0; e < 64; e++) {
            float v = Ls[tid * 65 + e];
            if (v > mv) { mv = v; mi = e; }     // first-occurrence argmax
        }
        float sum = 0.0f;
        float ev[64];
#pragma unroll
        for (int e = 0; e < 64; e++) { ev[e] = expf(Ls[tid * 65 + e] - mv); sum += ev[e]; }
        const float inv = 1.0f / sum;
        const int s = m0 + tid;
        g_idx[s]   = mi;
        g_gate1[s] = inv;                        // gate of argmax = exp(0)*inv
#pragma unroll
        for (int e = 0; e < 64; e++) pg[tid * 65 + e] = ev[e] * inv;
    }
    __syncthreads();
    {
        const int e = tid & 63, r = tid >> 6;    // 4 slices x 16 tokens
        float s2 = 0.0f;
#pragma unroll
        for (int j = 0; j < 16; j++) s2 += pg[(r * 16 + j) * 65 + e];
        red[r * 64 + e] = s2;
    }
    __syncthreads();
    if (tid < 64)
        g_partialGateSum[(size_t)blockIdx.x * 64 + tid] =
            red[tid] + red[64 + tid] + red[128 + tid] + red[192 + tid];
}

// ================= scan + aux + scatter (single block, MLP-prefetched) =================
__global__ void __launch_bounds__(1024) scan_scatter_kernel(float* __restrict__ combine,
                                                            float* __restrict__ maskp,
                                                            float* __restrict__ lauxp) {
    __shared__ int   hist[32 * E_EXP];
    __shared__ float red[16 * E_EXP];
    __shared__ int   cntS[E_EXP];
    __shared__ float vals[E_EXP];

    const int tid = threadIdx.x, lane = tid & 31, w = tid >> 5;
    const int base = w * 256;

    // ---- prefetch everything up front (independent LDGs, high MLP) ----
    int   eArr[8];
    float gArr[8];
#pragma unroll
    for (int g = 0; g < 8; g++) eArr[g] = g_idx[base + g * 32 + lane];
#pragma unroll
    for (int g = 0; g < 8; g++) gArr[g] = g_gate1[base + g * 32 + lane];
    const int pe = tid & 63, pr = tid >> 6;      // 16 slices x 64 experts
    float psv[8];
#pragma unroll
    for (int j = 0; j < 8; j++) psv[j] = g_partialGateSum[(size_t)(pr * 8 + j) * 64 + pe];

    hist[tid] = 0; hist[tid + 1024] = 0;
    __syncthreads();

    // phase 1: warp-local ordered ranks over 256 contiguous tokens
    int locArr[8];
#pragma unroll
    for (int g = 0; g < 8; g++) {
        const int e = eArr[g];
        unsigned mask = __match_any_sync(0xffffffffu, e);
        int rank = __popc(mask & ((1u << lane) - 1u));
        int bcnt = hist[w * E_EXP + e];
        locArr[g] = bcnt + rank;
        __syncwarp();
        if (lane == __ffs(mask) - 1) hist[w * E_EXP + e] = bcnt + __popc(mask);
        __syncwarp();
    }
    __syncthreads();

    // phase 2: exclusive prefix across warps per expert
    if (tid < E_EXP) {
        int running = 0;
        for (int ww = 0; ww < 32; ww++) {
            int c = hist[ww * E_EXP + tid];
            hist[ww * E_EXP + tid] = running;
            running += c;
        }
        cntS[tid] = running;
    }
    __syncthreads();

    // phase 3: scatter combine + mask (capacity drop)
#pragma unroll
    for (int g = 0; g < 8; g++) {
        const int s   = base + g * 32 + lane;
        const int e   = eArr[g];
        const int loc = hist[w * E_EXP + e] + locArr[g];
        if (loc < CAP) {
            const size_t off = (size_t)s * (E_EXP * CAP) + (size_t)e * CAP + loc;
            combine[off] = gArr[g];
            if (maskp) maskp[off] = 1.0f;
        }
    }

    // phase 4: aux loss (deterministic fixed order)
    {
        float s8 = 0.0f;
#pragma unroll
        for (int j = 0; j < 8; j++) s8 += psv[j];
        red[(size_t)pr * E_EXP + pe] = s8;
    }
    __syncthreads();
    if (tid < E_EXP) {
        float me = 0.0f;
#pragma unroll
        for (int r = 0; r < 16; r++) me += red[r * E_EXP + tid];
        me /= (float)S_TOK;
        float ce = (float)cntS[tid] / (float)S_TOK;
        vals[tid] = me * ce;
    }
    __syncthreads();
    if (tid == 0 && lauxp) {
        float a = 0.0f;
        for (int e = 0; e < E_EXP; e++) a += vals[e];
        lauxp[0] = a * (float)E_EXP;             // mean * E*E == sum * E
    }
}

// ---------------- launch ----------------
extern "C" void kernel_launch(void* const* d_in, const int* in_sizes, int n_in,
                              void* d_out, int out_size) {
    const float* x  = (const float*)d_in[0];   // [S, D]
    const float* wg = (const float*)d_in[1];   // [E, D]
    float* out = (float*)d_out;

    const long long SEC = (long long)S_TOK * E_EXP * CAP;  // 67,108,864
    float* lauxp   = nullptr;
    float* combine = out;
    float* maskp   = nullptr;
    if ((long long)out_size >= 1 + 2 * SEC) {          // [l_aux, combine, mask]
        lauxp = out; combine = out + 1; maskp = out + 1 + SEC;
    } else if ((long long)out_size == 1 + SEC) {       // [l_aux, combine]
        lauxp = out; combine = out + 1;
    }

    cudaMemsetAsync(d_out, 0, (size_t)out_size * sizeof(float));
    gemm_mma_kernel<<<S_TOK / 64, 256>>>(x, wg);
    scan_scatter_kernel<<<1, 1024>>>(combine, maskp, lauxp);
}

// round 12
// speedup vs baseline: 1.6647x; 1.1290x over previous
#include <cuda_runtime.h>
#include <cuda_bf16.h>
#include <cstdint>

#define S_TOK 8192
#define D_DIM 2048
#define E_EXP 64
#define CAP   128

// ---------------- scratch ----------------
__device__ int   g_idx[S_TOK];
__device__ float g_gate1[S_TOK];
__device__ int   g_rank[S_TOK];                   // intra-CTA rank within expert queue
__device__ int   g_cnt[128 * E_EXP];              // per-CTA expert histogram
__device__ int   g_base[128 * E_EXP];             // global exclusive prefix per (CTA, expert)
__device__ float g_partialGateSum[128 * E_EXP];   // per-CTA softmax expert sums
__device__ __nv_bfloat16 g_wgh[E_EXP * D_DIM];    // pre-split weights (hi)
__device__ __nv_bfloat16 g_wgl[E_EXP * D_DIM];    // pre-split weights (lo)

// ---------------- helpers ----------------
__device__ __forceinline__ void mma_bf16(float c[4], uint32_t a0, uint32_t a1, uint32_t a2, uint32_t a3,
                                         uint32_t b0, uint32_t b1) {
    asm volatile(
        "mma.sync.aligned.m16n8k16.row.col.f32.bf16.bf16.f32 "
        "{%0,%1,%2,%3}, {%4,%5,%6,%7}, {%8,%9}, {%0,%1,%2,%3};"
        : "+f"(c[0]), "+f"(c[1]), "+f"(c[2]), "+f"(c[3])
        : "r"(a0), "r"(a1), "r"(a2), "r"(a3), "r"(b0), "r"(b1));
}
__device__ __forceinline__ void split_bf16(float f, uint16_t& h, uint16_t& l) {
    __nv_bfloat16 bh = __float2bfloat16(f);
    float rem = f - __bfloat162float(bh);
    __nv_bfloat16 bl = __float2bfloat16(rem);
    h = __bfloat16_as_ushort(bh);
    l = __bfloat16_as_ushort(bl);
}
__device__ __forceinline__ uint64_t pack4(uint16_t a, uint16_t b, uint16_t c, uint16_t d) {
    return (uint64_t)a | ((uint64_t)b << 16) | ((uint64_t)c << 32) | ((uint64_t)d << 48);
}

// ================= K0: pre-split wg into bf16 hi/lo =================
__global__ void __launch_bounds__(256) split_wg_kernel(const float* __restrict__ wg) {
    const int i = (blockIdx.x * 256 + threadIdx.x) * 4;   // 128 blocks x 256 thr x 4 = 131072
    float4 v = *(const float4*)(wg + i);
    uint16_t h0, l0, h1, l1, h2, l2, h3, l3;
    split_bf16(v.x, h0, l0); split_bf16(v.y, h1, l1);
    split_bf16(v.z, h2, l2); split_bf16(v.w, h3, l3);
    ((uint64_t*)g_wgh)[i >> 2] = pack4(h0, h1, h2, h3);
    ((uint64_t*)g_wgl)[i >> 2] = pack4(l0, l1, l2, l3);
}

// ================= K1: HMMA GEMM (K-split warp groups) + softmax =================
// 128 CTAs x 512 threads. CTA tile: 64 tokens x 64 experts.
// Group g = warps (g*8..g*8+7) processes chunks {g, g+2, ...} in its own buffer set.
// 4-term bf16-split mma.sync into fp32 accumulators; groups combined in smem at end.
#define KC     64
#define NCH_G  16                   // chunks per group
#define SROWH  72                   // padded row: 72 bf16 = 144B
#define TILE_B (64 * SROWH * 2)     // 9216 B per tile
#define OFF_AH 0
#define OFF_AL (TILE_B)
#define OFF_BH (2 * TILE_B)
#define OFF_BL (3 * TILE_B)
#define BUFSET (4 * TILE_B)         // 36864 per group
#define SM_DYN (2 * BUFSET)         // 73728

__global__ void __launch_bounds__(512) gemm_mma_kernel(const float* __restrict__ x) {
    extern __shared__ __align__(16) char smbuf[];

    const int tid  = threadIdx.x;
    const int lane = tid & 31;
    const int w    = tid >> 5;
    const int g    = w >> 3;            // warp group 0/1
    const int wg_  = w & 7;
    const int gtid = tid & 255;         // thread id within group
    const int m0   = blockIdx.x * 64;
    const int M0   = (wg_ & 3) * 16;
    const int N0   = (wg_ >> 2) * 32;

    // staging coords: A 64x16 float4 (4/thread), B 64x8 uint4 (2/thread per h/l)
    int rr[4], cc[4];
#pragma unroll
    for (int t = 0; t < 4; t++) { int f = gtid + t * 256; rr[t] = f >> 4; cc[t] = (f & 15) * 4; }
    int br[2], b8[2];
#pragma unroll
    for (int t = 0; t < 2; t++) { int u = gtid + t * 256; br[t] = u >> 3; b8[t] = u & 7; }

    char* mybuf = smbuf + g * BUFSET;
    const uint32_t* AH32 = (const uint32_t*)(mybuf + OFF_AH);
    const uint32_t* AL32 = (const uint32_t*)(mybuf + OFF_AL);
    const uint32_t* BH32 = (const uint32_t*)(mybuf + OFF_BH);
    const uint32_t* BL32 = (const uint32_t*)(mybuf + OFF_BL);
    const uint4* WH4 = (const uint4*)g_wgh;
    const uint4* WL4 = (const uint4*)g_wgl;

    float acc[4][4];
#pragma unroll
    for (int nt = 0; nt < 4; nt++)
#pragma unroll
        for (int j = 0; j < 4; j++) acc[nt][j] = 0.0f;

    // prefetch first chunk of this group
    float4 av[4];
    uint4  bvh[2], bvl[2];
    {
        const int kc = g * KC;
#pragma unroll
        for (int t = 0; t < 4; t++)
            av[t] = *(const float4*)(x + (size_t)(m0 + rr[t]) * D_DIM + kc + cc[t]);
#pragma unroll
        for (int t = 0; t < 2; t++) {
            bvh[t] = WH4[br[t] * (D_DIM / 8) + (kc >> 3) + b8[t]];
            bvl[t] = WL4[br[t] * (D_DIM / 8) + (kc >> 3) + b8[t]];
        }
    }

    for (int it = 0; it < NCH_G; it++) {
        // ---- stage current chunk into this group's buffer ----
#pragma unroll
        for (int t = 0; t < 4; t++) {
            uint16_t h0, l0, h1, l1, h2, l2, h3, l3;
            const uint32_t off = (uint32_t)(rr[t] * SROWH + cc[t]) * 2;
            split_bf16(av[t].x, h0, l0); split_bf16(av[t].y, h1, l1);
            split_bf16(av[t].z, h2, l2); split_bf16(av[t].w, h3, l3);
            *(uint64_t*)(mybuf + OFF_AH + off) = pack4(h0, h1, h2, h3);
            *(uint64_t*)(mybuf + OFF_AL + off) = pack4(l0, l1, l2, l3);
        }
#pragma unroll
        for (int t = 0; t < 2; t++) {
            const uint32_t off = (uint32_t)(br[t] * SROWH) * 2 + b8[t] * 16;
            *(uint4*)(mybuf + OFF_BH + off) = bvh[t];
            *(uint4*)(mybuf + OFF_BL + off) = bvl[t];
        }
        __syncthreads();

        // ---- prefetch next chunk for this group ----
        if (it + 1 < NCH_G) {
            const int kc = (2 * (it + 1) + g) * KC;
#pragma unroll
            for (int t = 0; t < 4; t++)
                av[t] = *(const float4*)(x + (size_t)(m0 + rr[t]) * D_DIM + kc + cc[t]);
#pragma unroll
            for (int t = 0; t < 2; t++) {
                bvh[t] = WH4[br[t] * (D_DIM / 8) + (kc >> 3) + b8[t]];
                bvl[t] = WL4[br[t] * (D_DIM / 8) + (kc >> 3) + b8[t]];
            }
        }

        // ---- MMA: 4 k16-steps x 4 n8-tiles x 4 split terms ----
#pragma unroll
        for (int ks = 0; ks < 4; ks++) {
            const int kq = ks * 16 + (lane & 3) * 2;
            const int mA = M0 + (lane >> 2);
            const uint32_t ah0 = AH32[(mA * SROWH + kq) >> 1];
            const uint32_t ah1 = AH32[((mA + 8) * SROWH + kq) >> 1];
            const uint32_t ah2 = AH32[(mA * SROWH + kq + 8) >> 1];
            const uint32_t ah3 = AH32[((mA + 8) * SROWH + kq + 8) >> 1];
            const uint32_t al0 = AL32[(mA * SROWH + kq) >> 1];
            const uint32_t al1 = AL32[((mA + 8) * SROWH + kq) >> 1];
            const uint32_t al2 = AL32[(mA * SROWH + kq + 8) >> 1];
            const uint32_t al3 = AL32[((mA + 8) * SROWH + kq + 8) >> 1];
#pragma unroll
            for (int nt = 0; nt < 4; nt++) {
                const int nB = N0 + nt * 8 + (lane >> 2);
                const uint32_t bh0 = BH32[(nB * SROWH + kq) >> 1];
                const uint32_t bh1 = BH32[(nB * SROWH + kq + 8) >> 1];
                const uint32_t bl0 = BL32[(nB * SROWH + kq) >> 1];
                const uint32_t bl1 = BL32[(nB * SROWH + kq + 8) >> 1];
                mma_bf16(acc[nt], ah0, ah1, ah2, ah3, bh0, bh1);
                mma_bf16(acc[nt], ah0, ah1, ah2, ah3, bl0, bl1);
                mma_bf16(acc[nt], al0, al1, al2, al3, bh0, bh1);
                mma_bf16(acc[nt], al0, al1, al2, al3, bl0, bl1);
            }
        }
        __syncthreads();
    }

    // ---------- combine groups + softmax epilogue ----------
    float* Ls  = (float*)smbuf;            // [64][65]
    float* pg  = Ls + 64 * 65;             // [64][65]
    float* red = pg + 64 * 65;             // [8][64]
    int*   hw  = (int*)(red + 8 * 64);     // [2][64]

    const int r0 = M0 + (lane >> 2);
    const int cb = (lane & 3) * 2;
    if (g == 0) {
#pragma unroll
        for (int nt = 0; nt < 4; nt++) {
            const int c0 = N0 + nt * 8 + cb;
            Ls[r0 * 65 + c0]           = acc[nt][0];
            Ls[r0 * 65 + c0 + 1]       = acc[nt][1];
            Ls[(r0 + 8) * 65 + c0]     = acc[nt][2];
            Ls[(r0 + 8) * 65 + c0 + 1] = acc[nt][3];
        }
    }
    __syncthreads();
    if (g == 1) {
#pragma unroll
        for (int nt = 0; nt < 4; nt++) {
            const int c0 = N0 + nt * 8 + cb;
            Ls[r0 * 65 + c0]           += acc[nt][0];
            Ls[r0 * 65 + c0 + 1]       += acc[nt][1];
            Ls[(r0 + 8) * 65 + c0]     += acc[nt][2];
            Ls[(r0 + 8) * 65 + c0 + 1] += acc[nt][3];
        }
    }
    __syncthreads();

    int mi = 0;
    if (tid < 64) {
        float mv = -3.4e38f;
#pragma unroll
        for (int e = 0; e < 64; e++) {
            float v = Ls[tid * 65 + e];
            if (v > mv) { mv = v; mi = e; }     // first-occurrence argmax
        }
        float sum = 0.0f;
        float ev[64];
#pragma unroll
        for (int e = 0; e < 64; e++) { ev[e] = expf(Ls[tid * 65 + e] - mv); sum += ev[e]; }
        const float inv = 1.0f / sum;
        g_idx[m0 + tid]   = mi;
        g_gate1[m0 + tid] = inv;
#pragma unroll
        for (int e = 0; e < 64; e++) pg[tid * 65 + e] = ev[e] * inv;
    }
    if (tid < 128) hw[tid] = 0;
    __syncthreads();

    // ---- intra-CTA ordered rank + histogram (warps 0,1 = 64 tokens) ----
    int rank = 0;
    if (tid < 64) {
        unsigned mm = __match_any_sync(0xffffffffu, mi);
        rank = __popc(mm & ((1u << lane) - 1u));
        if (lane == __ffs(mm) - 1) hw[(tid >> 5) * 64 + mi] = __popc(mm);
    }
    __syncthreads();
    if (tid < 64) {
        if (tid >= 32) rank += hw[mi];          // add warp0's count for this expert
        g_rank[m0 + tid] = rank;
        g_cnt[blockIdx.x * 64 + tid] = hw[tid] + hw[64 + tid];
    }

    // ---- partial gate sums (512 threads: 8 slices x 8 tokens) ----
    {
        const int e = tid & 63, r = tid >> 6;
        float s2 = 0.0f;
#pragma unroll
        for (int j = 0; j < 8; j++) s2 += pg[(r * 8 + j) * 65 + e];
        red[r * 64 + e] = s2;
    }
    __syncthreads();
    if (tid < 64) {
        float s = 0.0f;
#pragma unroll
        for (int r = 0; r < 8; r++) s += red[r * 64 + tid];
        g_partialGateSum[(size_t)blockIdx.x * 64 + tid] = s;
    }
}

// ================= K2: cross-CTA prefix + aux loss (1 block) =================
__global__ void __launch_bounds__(1024) scan_base_kernel(float* __restrict__ lauxp) {
    __shared__ int   ss[16 * E_EXP];
    __shared__ float ps[16 * E_EXP];
    __shared__ int   cntS[E_EXP];
    __shared__ float vals[E_EXP];

    const int tid = threadIdx.x;
    const int e = tid & 63, r = tid >> 6;       // 16 slices x 8 CTAs

    int c[8], pre[8];
    float p[8];
#pragma unroll
    for (int j = 0; j < 8; j++) c[j] = g_cnt[(r * 8 + j) * 64 + e];
#pragma unroll
    for (int j = 0; j < 8; j++) p[j] = g_partialGateSum[(size_t)(r * 8 + j) * 64 + e];

    int s = 0;
#pragma unroll
    for (int j = 0; j < 8; j++) { pre[j] = s; s += c[j]; }
    ss[r * 64 + e] = s;
    float fs = 0.0f;
#pragma unroll
    for (int j = 0; j < 8; j++) fs += p[j];
    ps[r * 64 + e] = fs;
    __syncthreads();

    if (tid < 64) {
        int running = 0;
        for (int rr = 0; rr < 16; rr++) {
            int t = ss[rr * 64 + tid];
            ss[rr * 64 + tid] = running;
            running += t;
        }
        cntS[tid] = running;
    }
    __syncthreads();

    const int base0 = ss[r * 64 + e];
#pragma unroll
    for (int j = 0; j < 8; j++) g_base[(r * 8 + j) * 64 + e] = base0 + pre[j];

    if (tid < 64) {
        float me = 0.0f;
#pragma unroll
        for (int rr = 0; rr < 16; rr++) me += ps[rr * 64 + tid];
        me /= (float)S_TOK;
        float ce = (float)cntS[tid] / (float)S_TOK;
        vals[tid] = me * ce;
    }
    __syncthreads();
    if (tid == 0 && lauxp) {
        float a = 0.0f;
        for (int ee = 0; ee < E_EXP; ee++) a += vals[ee];
        lauxp[0] = a * (float)E_EXP;            // mean * E*E == sum * E
    }
}

// ================= K3: scatter combine + mask (32 blocks) =================
__global__ void __launch_bounds__(256) scatter_kernel(float* __restrict__ combine,
                                                      float* __restrict__ maskp) {
    const int s = blockIdx.x * 256 + threadIdx.x;
    const int e = g_idx[s];
    const int loc = g_base[(s >> 6) * 64 + e] + g_rank[s];
    if (loc < CAP) {
        const size_t off = (size_t)s * (E_EXP * CAP) + (size_t)e * CAP + loc;
        combine[off] = g_gate1[s];
        if (maskp) maskp[off] = 1.0f;
    }
}

// ---------------- launch ----------------
extern "C" void kernel_launch(void* const* d_in, const int* in_sizes, int n_in,
                              void* d_out, int out_size) {
    const float* x  = (const float*)d_in[0];   // [S, D]
    const float* wg = (const float*)d_in[1];   // [E, D]
    float* out = (float*)d_out;

    const long long SEC = (long long)S_TOK * E_EXP * CAP;  // 67,108,864
    float* lauxp   = nullptr;
    float* combine = out;
    float* maskp   = nullptr;
    if ((long long)out_size >= 1 + 2 * SEC) {          // [l_aux, combine, mask]
        lauxp = out; combine = out + 1; maskp = out + 1 + SEC;
    } else if ((long long)out_size == 1 + SEC) {       // [l_aux, combine]
        lauxp = out; combine = out + 1;
    }

    cudaFuncSetAttribute(gemm_mma_kernel, cudaFuncAttributeMaxDynamicSharedMemorySize, SM_DYN);

    split_wg_kernel<<<128, 256>>>(wg);
    cudaMemsetAsync(d_out, 0, (size_t)out_size * sizeof(float));
    gemm_mma_kernel<<<128, 512, SM_DYN>>>(x);
    scan_base_kernel<<<1, 1024>>>(lauxp);
    scatter_kernel<<<S_TOK / 256, 256>>>(combine, maskp);
}

// round 13
// speedup vs baseline: 1.6920x; 1.0164x over previous
#include <cuda_runtime.h>
#include <cuda_bf16.h>
#include <cstdint>

#define S_TOK 8192
#define D_DIM 2048
#define E_EXP 64
#define CAP   128

// ---------------- scratch ----------------
__device__ int   g_idx[S_TOK];
__device__ float g_gate1[S_TOK];
__device__ int   g_rank[S_TOK];                   // intra-CTA rank within expert queue
__device__ int   g_cnt[128 * E_EXP];              // per-CTA expert histogram
__device__ float g_partialGateSum[128 * E_EXP];   // per-CTA softmax expert sums
__device__ __nv_bfloat16 g_wgh[E_EXP * D_DIM];    // pre-split weights (hi)
__device__ __nv_bfloat16 g_wgl[E_EXP * D_DIM];    // pre-split weights (lo)

// ---------------- helpers ----------------
__device__ __forceinline__ void mma_bf16(float c[4], uint32_t a0, uint32_t a1, uint32_t a2, uint32_t a3,
                                         uint32_t b0, uint32_t b1) {
    asm volatile(
        "mma.sync.aligned.m16n8k16.row.col.f32.bf16.bf16.f32 "
        "{%0,%1,%2,%3}, {%4,%5,%6,%7}, {%8,%9}, {%0,%1,%2,%3};"
        : "+f"(c[0]), "+f"(c[1]), "+f"(c[2]), "+f"(c[3])
        : "r"(a0), "r"(a1), "r"(a2), "r"(a3), "r"(b0), "r"(b1));
}
__device__ __forceinline__ void split_bf16(float f, uint16_t& h, uint16_t& l) {
    __nv_bfloat16 bh = __float2bfloat16(f);
    float rem = f - __bfloat162float(bh);
    __nv_bfloat16 bl = __float2bfloat16(rem);
    h = __bfloat16_as_ushort(bh);
    l = __bfloat16_as_ushort(bl);
}
__device__ __forceinline__ uint64_t pack4(uint16_t a, uint16_t b, uint16_t c, uint16_t d) {
    return (uint64_t)a | ((uint64_t)b << 16) | ((uint64_t)c << 32) | ((uint64_t)d << 48);
}

// ================= K0: pre-split wg into bf16 hi/lo =================
__global__ void __launch_bounds__(256) split_wg_kernel(const float* __restrict__ wg) {
    const int i = (blockIdx.x * 256 + threadIdx.x) * 4;   // 128 x 256 x 4 = 131072
    float4 v = *(const float4*)(wg + i);
    uint16_t h0, l0, h1, l1, h2, l2, h3, l3;
    split_bf16(v.x, h0, l0); split_bf16(v.y, h1, l1);
    split_bf16(v.z, h2, l2); split_bf16(v.w, h3, l3);
    ((uint64_t*)g_wgh)[i >> 2] = pack4(h0, h1, h2, h3);
    ((uint64_t*)g_wgl)[i >> 2] = pack4(l0, l1, l2, l3);
}

// ================= K1: fused HMMA GEMM + output zeroing =================
// Blocks 0..127  : gemm role (512 thr, 73.7KB smem, reg-heavy) -> exclusive SMs
// Blocks 128+    : zero role (streaming STG.128) -> free SMs, then backfill
// Register pressure of the gemm path prevents zero blocks from co-residing
// with gemm CTAs -> no round-2-style issue-slot interference.
#define GEMM_BLOCKS 128
#define ZERO_BLOCKS 1024
#define KC     64
#define NCH_G  16                   // chunks per warp group
#define SROWH  72                   // padded row: 72 bf16 = 144B
#define TILE_B (64 * SROWH * 2)     // 9216 B per tile
#define OFF_AH 0
#define OFF_AL (TILE_B)
#define OFF_BH (2 * TILE_B)
#define OFF_BL (3 * TILE_B)
#define BUFSET (4 * TILE_B)         // 36864 per group
#define SM_DYN (2 * BUFSET)         // 73728

__global__ void __launch_bounds__(512) fused_gemm_zero_kernel(const float* __restrict__ x,
                                                              float* __restrict__ out,
                                                              long long out_elems) {
    // ---------- zero role ----------
    if (blockIdx.x >= GEMM_BLOCKS) {
        const long long zb = blockIdx.x - GEMM_BLOCKS;
        const long long total4 = out_elems >> 2;
        float4* o4 = (float4*)out;
        const float4 z = make_float4(0.f, 0.f, 0.f, 0.f);
        const long long stride = (long long)ZERO_BLOCKS * 512;
        for (long long i = zb * 512 + threadIdx.x; i < total4; i += stride)
            __stcs(o4 + i, z);
        if (zb == 0 && threadIdx.x == 0)
            for (long long i = total4 * 4; i < out_elems; i++) out[i] = 0.f;
        return;
    }

    // ---------- gemm role (identical math to round-12 kernel) ----------
    extern __shared__ __align__(16) char smbuf[];

    const int tid  = threadIdx.x;
    const int lane = tid & 31;
    const int w    = tid >> 5;
    const int g    = w >> 3;            // warp group 0/1 (K-split)
    const int wg_  = w & 7;
    const int gtid = tid & 255;
    const int m0   = blockIdx.x * 64;
    const int M0   = (wg_ & 3) * 16;
    const int N0   = (wg_ >> 2) * 32;

    int rr[4], cc[4];
#pragma unroll
    for (int t = 0; t < 4; t++) { int f = gtid + t * 256; rr[t] = f >> 4; cc[t] = (f & 15) * 4; }
    int br[2], b8[2];
#pragma unroll
    for (int t = 0; t < 2; t++) { int u = gtid + t * 256; br[t] = u >> 3; b8[t] = u & 7; }

    char* mybuf = smbuf + g * BUFSET;
    const uint32_t* AH32 = (const uint32_t*)(mybuf + OFF_AH);
    const uint32_t* AL32 = (const uint32_t*)(mybuf + OFF_AL);
    const uint32_t* BH32 = (const uint32_t*)(mybuf + OFF_BH);
    const uint32_t* BL32 = (const uint32_t*)(mybuf + OFF_BL);
    const uint4* WH4 = (const uint4*)g_wgh;
    const uint4* WL4 = (const uint4*)g_wgl;

    float acc[4][4];
#pragma unroll
    for (int nt = 0; nt < 4; nt++)
#pragma unroll
        for (int j = 0; j < 4; j++) acc[nt][j] = 0.0f;

    float4 av[4];
    uint4  bvh[2], bvl[2];
    {
        const int kc = g * KC;
#pragma unroll
        for (int t = 0; t < 4; t++)
            av[t] = *(const float4*)(x + (size_t)(m0 + rr[t]) * D_DIM + kc + cc[t]);
#pragma unroll
        for (int t = 0; t < 2; t++) {
            bvh[t] = WH4[br[t] * (D_DIM / 8) + (kc >> 3) + b8[t]];
            bvl[t] = WL4[br[t] * (D_DIM / 8) + (kc >> 3) + b8[t]];
        }
    }

    for (int it = 0; it < NCH_G; it++) {
#pragma unroll
        for (int t = 0; t < 4; t++) {
            uint16_t h0, l0, h1, l1, h2, l2, h3, l3;
            const uint32_t off = (uint32_t)(rr[t] * SROWH + cc[t]) * 2;
            split_bf16(av[t].x, h0, l0); split_bf16(av[t].y, h1, l1);
            split_bf16(av[t].z, h2, l2); split_bf16(av[t].w, h3, l3);
            *(uint64_t*)(mybuf + OFF_AH + off) = pack4(h0, h1, h2, h3);
            *(uint64_t*)(mybuf + OFF_AL + off) = pack4(l0, l1, l2, l3);
        }
#pragma unroll
        for (int t = 0; t < 2; t++) {
            const uint32_t off = (uint32_t)(br[t] * SROWH) * 2 + b8[t] * 16;
            *(uint4*)(mybuf + OFF_BH + off) = bvh[t];
            *(uint4*)(mybuf + OFF_BL + off) = bvl[t];
        }
        __syncthreads();

        if (it + 1 < NCH_G) {
            const int kc = (2 * (it + 1) + g) * KC;
#pragma unroll
            for (int t = 0; t < 4; t++)
                av[t] = *(const float4*)(x + (size_t)(m0 + rr[t]) * D_DIM + kc + cc[t]);
#pragma unroll
            for (int t = 0; t < 2; t++) {
                bvh[t] = WH4[br[t] * (D_DIM / 8) + (kc >> 3) + b8[t]];
                bvl[t] = WL4[br[t] * (D_DIM / 8) + (kc >> 3) + b8[t]];
            }
        }

#pragma unroll
        for (int ks = 0; ks < 4; ks++) {
            const int kq = ks * 16 + (lane & 3) * 2;
            const int mA = M0 + (lane >> 2);
            const uint32_t ah0 = AH32[(mA * SROWH + kq) >> 1];
            const uint32_t ah1 = AH32[((mA + 8) * SROWH + kq) >> 1];
            const uint32_t ah2 = AH32[(mA * SROWH + kq + 8) >> 1];
            const uint32_t ah3 = AH32[((mA + 8) * SROWH + kq + 8) >> 1];
            const uint32_t al0 = AL32[(mA * SROWH + kq) >> 1];
            const uint32_t al1 = AL32[((mA + 8) * SROWH + kq) >> 1];
            const uint32_t al2 = AL32[(mA * SROWH + kq + 8) >> 1];
            const uint32_t al3 = AL32[((mA + 8) * SROWH + kq + 8) >> 1];
#pragma unroll
            for (int nt = 0; nt < 4; nt++) {
                const int nB = N0 + nt * 8 + (lane >> 2);
                const uint32_t bh0 = BH32[(nB * SROWH + kq) >> 1];
                const uint32_t bh1 = BH32[(nB * SROWH + kq + 8) >> 1];
                const uint32_t bl0 = BL32[(nB * SROWH + kq) >> 1];
                const uint32_t bl1 = BL32[(nB * SROWH + kq + 8) >> 1];
                mma_bf16(acc[nt], ah0, ah1, ah2, ah3, bh0, bh1);
                mma_bf16(acc[nt], ah0, ah1, ah2, ah3, bl0, bl1);
                mma_bf16(acc[nt], al0, al1, al2, al3, bh0, bh1);
                mma_bf16(acc[nt], al0, al1, al2, al3, bl0, bl1);
            }
        }
        __syncthreads();
    }

    // ---------- combine groups + softmax + rank/hist epilogue ----------
    float* Ls  = (float*)smbuf;            // [64][65]
    float* pg  = Ls + 64 * 65;             // [64][65]
    float* red = pg + 64 * 65;             // [8][64]
    int*   hw  = (int*)(red + 8 * 64);     // [2][64]

    const int r0 = M0 + (lane >> 2);
    const int cb = (lane & 3) * 2;
    if (g == 0) {
#pragma unroll
        for (int nt = 0; nt < 4; nt++) {
            const int c0 = N0 + nt * 8 + cb;
            Ls[r0 * 65 + c0]           = acc[nt][0];
            Ls[r0 * 65 + c0 + 1]       = acc[nt][1];
            Ls[(r0 + 8) * 65 + c0]     = acc[nt][2];
            Ls[(r0 + 8) * 65 + c0 + 1] = acc[nt][3];
        }
    }
    __syncthreads();
    if (g == 1) {
#pragma unroll
        for (int nt = 0; nt < 4; nt++) {
            const int c0 = N0 + nt * 8 + cb;
            Ls[r0 * 65 + c0]           += acc[nt][0];
            Ls[r0 * 65 + c0 + 1]       += acc[nt][1];
            Ls[(r0 + 8) * 65 + c0]     += acc[nt][2];
            Ls[(r0 + 8) * 65 + c0 + 1] += acc[nt][3];
        }
    }
    __syncthreads();

    int mi = 0;
    if (tid < 64) {
        float mv = -3.4e38f;
#pragma unroll
        for (int e = 0; e < 64; e++) {
            float v = Ls[tid * 65 + e];
            if (v > mv) { mv = v; mi = e; }     // first-occurrence argmax
        }
        float sum = 0.0f;
        float ev[64];
#pragma unroll
        for (int e = 0; e < 64; e++) { ev[e] = expf(Ls[tid * 65 + e] - mv); sum += ev[e]; }
        const float inv = 1.0f / sum;
        g_idx[m0 + tid]   = mi;
        g_gate1[m0 + tid] = inv;
#pragma unroll
        for (int e = 0; e < 64; e++) pg[tid * 65 + e] = ev[e] * inv;
    }
    if (tid < 128) hw[tid] = 0;
    __syncthreads();

    int rank = 0;
    if (tid < 64) {
        unsigned mm = __match_any_sync(0xffffffffu, mi);
        rank = __popc(mm & ((1u << lane) - 1u));
        if (lane == __ffs(mm) - 1) hw[(tid >> 5) * 64 + mi] = __popc(mm);
    }
    __syncthreads();
    if (tid < 64) {
        if (tid >= 32) rank += hw[mi];
        g_rank[m0 + tid] = rank;
        g_cnt[blockIdx.x * 64 + tid] = hw[tid] + hw[64 + tid];
    }

    {
        const int e = tid & 63, r = tid >> 6;
        float s2 = 0.0f;
#pragma unroll
        for (int j = 0; j < 8; j++) s2 += pg[(r * 8 + j) * 65 + e];
        red[r * 64 + e] = s2;
    }
    __syncthreads();
    if (tid < 64) {
        float s = 0.0f;
#pragma unroll
        for (int r = 0; r < 8; r++) s += red[r * 64 + tid];
        g_partialGateSum[(size_t)blockIdx.x * 64 + tid] = s;
    }
}

// ================= K2: prefix + aux + scatter (1 block; zeros already done) =================
__global__ void __launch_bounds__(1024) scan_scatter_kernel(float* __restrict__ combine,
                                                            float* __restrict__ maskp,
                                                            float* __restrict__ lauxp) {
    __shared__ int   bases[128 * E_EXP];   // 32 KB: global base per (CTA, expert)
    __shared__ int   ss[16 * E_EXP];
    __shared__ float ps[16 * E_EXP];
    __shared__ int   cntS[E_EXP];
    __shared__ float vals[E_EXP];

    const int tid = threadIdx.x;
    const int e = tid & 63, r = tid >> 6;       // 16 slices x 8 CTAs

    // ---- prefetch token data for scatter (independent LDGs, high MLP) ----
    int eA[8], rkA[8];
    float gA[8];
#pragma unroll
    for (int j = 0; j < 8; j++) eA[j]  = g_idx[tid + j * 1024];
#pragma unroll
    for (int j = 0; j < 8; j++) rkA[j] = g_rank[tid + j * 1024];
#pragma unroll
    for (int j = 0; j < 8; j++) gA[j]  = g_gate1[tid + j * 1024];

    int c[8], pre[8];
    float p[8];
#pragma unroll
    for (int j = 0; j < 8; j++) c[j] = g_cnt[(r * 8 + j) * 64 + e];
#pragma unroll
    for (int j = 0; j < 8; j++) p[j] = g_partialGateSum[(size_t)(r * 8 + j) * 64 + e];

    int s = 0;
#pragma unroll
    for (int j = 0; j < 8; j++) { pre[j] = s; s += c[j]; }
    ss[r * 64 + e] = s;
    float fs = 0.0f;
#pragma unroll
    for (int j = 0; j < 8; j++) fs += p[j];
    ps[r * 64 + e] = fs;
    __syncthreads();

    if (tid < 64) {
        int running = 0;
        for (int rr = 0; rr < 16; rr++) {
            int t = ss[rr * 64 + tid];
            ss[rr * 64 + tid] = running;
            running += t;
        }
        cntS[tid] = running;
    }
    __syncthreads();

    const int base0 = ss[r * 64 + e];
#pragma unroll
    for (int j = 0; j < 8; j++) bases[(r * 8 + j) * 64 + e] = base0 + pre[j];

    if (tid < 64) {
        float me = 0.0f;
#pragma unroll
        for (int rr = 0; rr < 16; rr++) me += ps[rr * 64 + tid];
        me /= (float)S_TOK;
        float ce = (float)cntS[tid] / (float)S_TOK;
        vals[tid] = me * ce;
    }
    __syncthreads();

    // ---- scatter ----
#pragma unroll
    for (int j = 0; j < 8; j++) {
        const int stok = tid + j * 1024;
        const int ee   = eA[j];
        const int loc  = bases[(stok >> 6) * 64 + ee] + rkA[j];
        if (loc < CAP) {
            const size_t off = (size_t)stok * (E_EXP * CAP) + (size_t)ee * CAP + loc;
            combine[off] = gA[j];
            if (maskp) maskp[off] = 1.0f;
        }
    }

    if (tid == 0 && lauxp) {
        float a = 0.0f;
        for (int ee = 0; ee < E_EXP; ee++) a += vals[ee];
        lauxp[0] = a * (float)E_EXP;            // mean * E*E == sum * E
    }
}

// ---------------- launch ----------------
extern "C" void kernel_launch(void* const* d_in, const int* in_sizes, int n_in,
                              void* d_out, int out_size) {
    const float* x  = (const float*)d_in[0];   // [S, D]
    const float* wg = (const float*)d_in[1];   // [E, D]
    float* out = (float*)d_out;

    const long long SEC = (long long)S_TOK * E_EXP * CAP;  // 67,108,864
    float* lauxp   = nullptr;
    float* combine = out;
    float* maskp   = nullptr;
    if ((long long)out_size >= 1 + 2 * SEC) {          // [l_aux, combine, mask]
        lauxp = out; combine = out + 1; maskp = out + 1 + SEC;
    } else if ((long long)out_size == 1 + SEC) {       // [l_aux, combine]
        lauxp = out; combine = out + 1;
    }

    cudaFuncSetAttribute(fused_gemm_zero_kernel, cudaFuncAttributeMaxDynamicSharedMemorySize, SM_DYN);

    split_wg_kernel<<<128, 256>>>(wg);
    fused_gemm_zero_kernel<<<GEMM_BLOCKS + ZERO_BLOCKS, 512, SM_DYN>>>(x, out, (long long)out_size);
    scan_scatter_kernel<<<1, 1024>>>(combine, maskp, lauxp);
}